// round 15
// baseline (speedup 1.0000x reference)
#include <cuda_runtime.h>
#include <cuda_fp16.h>
#include <cstdint>

#define BATCH 32
#define TT    1024
#define DD    512
#define HH    512
#define OO    256
#define MTOT  (BATCH * TT)   // 32768
#define BGRP  16             // batches per pipeline group
#define MGRP  (BGRP * TT)    // 16384 rows per group

__device__ float  g_I0[(size_t)MTOT * HH];
__device__ __half g_S1[(size_t)MTOT * HH];
__device__ float  g_SF[BATCH * HH];
__device__ __half g_xh[(size_t)MTOT * DD];
__device__ __half g_xl[(size_t)MTOT * DD];
__device__ __half g_w0h[HH * DD], g_w0l[HH * DD];
__device__ __half g_w1h[HH * HH], g_w1l[HH * HH];

#define INV2048 4.8828125e-4f
#define PHK 72                     // smem row pitch in halves for BK=64

// ---------------------------------------------------------------------------
__device__ __forceinline__ uint32_t smem_u32(const void* p) {
    uint32_t a;
    asm("{ .reg .u64 t; cvta.to.shared.u64 t, %1; cvt.u32.u64 %0, t; }"
        : "=r"(a) : "l"(p));
    return a;
}
__device__ __forceinline__ void cp_async16(uint32_t dst, const void* src) {
    asm volatile("cp.async.cg.shared.global [%0], [%1], 16;" :: "r"(dst), "l"(src));
}
#define CP_COMMIT()  asm volatile("cp.async.commit_group;" ::: "memory")
#define CP_WAIT(n)   asm volatile("cp.async.wait_group %0;" :: "n"(n) : "memory")

__device__ __forceinline__ void mma_f16(float* d, const uint32_t* a, const uint32_t* b) {
    asm volatile(
        "mma.sync.aligned.m16n8k16.row.col.f32.f16.f16.f32 "
        "{%0,%1,%2,%3}, {%4,%5,%6,%7}, {%8,%9}, {%0,%1,%2,%3};"
        : "+f"(d[0]), "+f"(d[1]), "+f"(d[2]), "+f"(d[3])
        : "r"(a[0]), "r"(a[1]), "r"(a[2]), "r"(a[3]), "r"(b[0]), "r"(b[1]));
}
#define LDSM_X4(r0, r1, r2, r3, addr) \
    asm volatile("ldmatrix.sync.aligned.m8n8.x4.shared.b16 {%0,%1,%2,%3}, [%4];" \
                 : "=r"(r0), "=r"(r1), "=r"(r2), "=r"(r3) : "r"(addr))

// ---------------------------------------------------------------------------
__global__ __launch_bounds__(256) void conv_split(const float* __restrict__ X,
                                                  __half* __restrict__ Xh,
                                                  __half* __restrict__ Xl)
{
    int i = (blockIdx.x * 256 + threadIdx.x) * 4;
    float4 v = *(const float4*)(X + i);
    __half h0 = __float2half_rn(v.x), h1 = __float2half_rn(v.y);
    __half h2 = __float2half_rn(v.z), h3 = __float2half_rn(v.w);
    __half l0 = __float2half_rn((v.x - __half2float(h0)) * 2048.f);
    __half l1 = __float2half_rn((v.y - __half2float(h1)) * 2048.f);
    __half l2 = __float2half_rn((v.z - __half2float(h2)) * 2048.f);
    __half l3 = __float2half_rn((v.w - __half2float(h3)) * 2048.f);
    __half2 hv0 = __halves2half2(h0, h1), hv1 = __halves2half2(h2, h3);
    __half2 lv0 = __halves2half2(l0, l1), lv1 = __halves2half2(l2, l3);
    uint2 ho = { *(uint32_t*)&hv0, *(uint32_t*)&hv1 };
    uint2 lo = { *(uint32_t*)&lv0, *(uint32_t*)&lv1 };
    *(uint2*)(Xh + i) = ho;
    *(uint2*)(Xl + i) = lo;
}

// ---------------------------------------------------------------------------
// fp16 GEMM — R10/R13 champion: CTA 128x128, BK=64, 512 thr / 16 warps,
// 3-stage cp.async, B frags double-buffered, two barriers per chunk.
// Dual fp32 accumulators (H + L/2048); bitwise-stable.
// ---------------------------------------------------------------------------
struct BFrag { uint32_t bh[4][2]; uint32_t bl[4][2]; };

template <bool SPLIT_A>
__global__ __launch_bounds__(512, 1) void gemm_f16(
    const __half* __restrict__ Ahg, const __half* __restrict__ Alg,
    const __half* __restrict__ Bhg, const __half* __restrict__ Blg,
    const float* __restrict__ bias, float* __restrict__ C, int K)
{
    constexpr int TILE_H = 128 * PHK;
    constexpr int NT     = SPLIT_A ? 4 : 3;
    constexpr int STG_H  = NT * TILE_H;
    constexpr int OFF_AH = 0;
    constexpr int OFF_AL = TILE_H;               // iff SPLIT_A
    constexpr int OFF_BH = (SPLIT_A ? 2 : 1) * TILE_H;
    constexpr int OFF_BL = OFF_BH + TILE_H;
    extern __shared__ __half sh[];
    const uint32_t sb = smem_u32(sh);

    const int tid = threadIdx.x, lid = tid & 31, wid = tid >> 5;
    const int bm = blockIdx.y * 128, bn = blockIdx.x * 128;
    const int warp_m = (wid >> 2) * 32, warp_n = (wid & 3) * 32;

    float accH[2][4][4], accL[2][4][4];
#pragma unroll
    for (int i = 0; i < 2; i++)
#pragma unroll
        for (int j = 0; j < 4; j++)
#pragma unroll
            for (int f = 0; f < 4; f++) { accH[i][j][f] = 0.f; accL[i][j][f] = 0.f; }

    const int NC = K / 64;
    const int lr  = tid >> 3;
    const int lc8 = (tid & 7) * 8;

    auto ld_tile = [&](const __half* G, int grow, int kc, uint32_t dst_halves,
                       uint32_t base) {
        cp_async16(base + (dst_halves + (uint32_t)lr * PHK + lc8) * 2,
                   G + (size_t)(grow + lr) * K + kc + lc8);
        cp_async16(base + (dst_halves + (uint32_t)(lr + 64) * PHK + lc8) * 2,
                   G + (size_t)(grow + lr + 64) * K + kc + lc8);
    };
    auto load_stage = [&](int c) {
        const int kc = c * 64;
        uint32_t base = sb + (uint32_t)(c % 3) * STG_H * 2;
        ld_tile(Ahg, bm, kc, OFF_AH, base);
        if (SPLIT_A) ld_tile(Alg, bm, kc, OFF_AL, base);
        ld_tile(Bhg, bn, kc, OFF_BH, base);
        ld_tile(Blg, bn, kc, OFF_BL, base);
        CP_COMMIT();
    };

    const uint32_t arow = ((uint32_t)(warp_m + (lid & 15)) * PHK + ((lid >> 4) << 3)) * 2;
    const uint32_t brow = ((uint32_t)(warp_n + ((lid >> 4) << 3) + (lid & 7)) * PHK
                          + (((lid >> 3) & 1) << 3)) * 2;

    uint32_t ah[2][4], al[2][4];
    auto ldA = [&](uint32_t stage_base, int ks) {
        uint32_t a0 = stage_base + OFF_AH * 2 + arow + (uint32_t)(ks * 16) * 2;
        LDSM_X4(ah[0][0], ah[0][1], ah[0][2], ah[0][3], a0);
        LDSM_X4(ah[1][0], ah[1][1], ah[1][2], ah[1][3], a0 + 16u * PHK * 2);
        if (SPLIT_A) {
            uint32_t a1 = stage_base + OFF_AL * 2 + arow + (uint32_t)(ks * 16) * 2;
            LDSM_X4(al[0][0], al[0][1], al[0][2], al[0][3], a1);
            LDSM_X4(al[1][0], al[1][1], al[1][2], al[1][3], a1 + 16u * PHK * 2);
        }
    };
    auto ldB = [&](BFrag& f, uint32_t stage_base, int ks) {
        uint32_t bH = stage_base + OFF_BH * 2 + brow + (uint32_t)(ks * 16) * 2;
        uint32_t bL = stage_base + OFF_BL * 2 + brow + (uint32_t)(ks * 16) * 2;
#pragma unroll
        for (int jp = 0; jp < 2; jp++) {
            uint32_t off = (uint32_t)jp * 16 * PHK * 2;
            LDSM_X4(f.bh[2*jp][0], f.bh[2*jp][1], f.bh[2*jp+1][0], f.bh[2*jp+1][1], bH + off);
            LDSM_X4(f.bl[2*jp][0], f.bl[2*jp][1], f.bl[2*jp+1][0], f.bl[2*jp+1][1], bL + off);
        }
    };
    auto mma_all = [&](const BFrag& f) {
#pragma unroll
        for (int i = 0; i < 2; i++)
#pragma unroll
            for (int j = 0; j < 4; j++)
                mma_f16(accH[i][j], ah[i], f.bh[j]);
#pragma unroll
        for (int i = 0; i < 2; i++)
#pragma unroll
            for (int j = 0; j < 4; j++)
                mma_f16(accL[i][j], ah[i], f.bl[j]);
        if (SPLIT_A) {
#pragma unroll
            for (int i = 0; i < 2; i++)
#pragma unroll
                for (int j = 0; j < 4; j++)
                    mma_f16(accL[i][j], al[i], f.bh[j]);
        }
    };

    load_stage(0); load_stage(1); load_stage(2);

    BFrag fb0, fb1;
    CP_WAIT(2);
    __syncthreads();
    ldB(fb0, sb, 0);

    for (int c = 0; c < NC; c++) {
        if (c < NC - 2) { CP_WAIT(1); } else { CP_WAIT(0); }
        __syncthreads();
        uint32_t st_c  = sb + (uint32_t)(c % 3) * STG_H * 2;
        uint32_t st_c1 = sb + (uint32_t)((c + 1) % 3) * STG_H * 2;

        ldA(st_c, 0); ldB(fb1, st_c, 1); mma_all(fb0);
        ldA(st_c, 1); ldB(fb0, st_c, 2); mma_all(fb1);
        ldA(st_c, 2); ldB(fb1, st_c, 3); mma_all(fb0);
        ldA(st_c, 3);
        if (c + 1 < NC) ldB(fb0, st_c1, 0);
        mma_all(fb1);

        __syncthreads();
        if (c + 3 < NC) load_stage(c + 3);
    }

#pragma unroll
    for (int i = 0; i < 2; i++) {
        int row0 = bm + warp_m + i * 16 + (lid >> 2);
#pragma unroll
        for (int j = 0; j < 4; j++) {
            int col = bn + warp_n + j * 8 + (lid & 3) * 2;
            float b0 = bias[col], b1 = bias[col + 1];
            float2 v0 = { accH[i][j][0] + accL[i][j][0] * INV2048 + b0,
                          accH[i][j][1] + accL[i][j][1] * INV2048 + b1 };
            float2 v1 = { accH[i][j][2] + accL[i][j][2] * INV2048 + b0,
                          accH[i][j][3] + accL[i][j][3] * INV2048 + b1 };
            *(float2*)(C + (size_t)row0 * HH + col) = v0;
            *(float2*)(C + (size_t)(row0 + 8) * HH + col) = v1;
        }
    }
}

// ---------------------------------------------------------------------------
// LIF scan (per batch-group), speculative dual-path update (bit-identical).
// ---------------------------------------------------------------------------
template <bool WRITE_ALL>
__global__ __launch_bounds__(128) void lif_scan(const float* __restrict__ I,
                                                __half* __restrict__ S,
                                                float* __restrict__ SF)
{
    extern __shared__ float buf[];
    const int tid = threadIdx.x;
    const int b  = blockIdx.x >> 2;                 // batch within group
    const int h0 = (blockIdx.x & 3) * 128;
    const float* src = I + (size_t)b * TT * HH + h0;
    __half* sdst = WRITE_ALL ? (S + (size_t)b * TT * HH + h0 + tid) : nullptr;

    const uint32_t sb = smem_u32(buf);
    constexpr int STAGE_W = 64 * 128;

    auto load_stage = [&](int st) {
        const float* g = src + (size_t)st * 64 * HH;
        uint32_t d = sb + (uint32_t)(st & 3) * STAGE_W * 4;
#pragma unroll
        for (int s = 0; s < 16; s++) {
            int c = tid + s * 128;
            int t = c >> 5, off = (c & 31) * 4;
            cp_async16(d + (uint32_t)(t * 128 + off) * 4, g + (size_t)t * HH + off);
        }
        CP_COMMIT();
    };

    load_stage(0); load_stage(1); load_stage(2); load_stage(3);

    float u = 0.f;
    bool sflag = false;
    for (int st = 0; st < 16; st++) {
        CP_WAIT(3);
        __syncthreads();
        const float* stage = buf + (st & 3) * STAGE_W;
#pragma unroll
        for (int t = 0; t < 64; t++) {
            float iv = stage[t * 128 + tid];
            float d1 = __fadd_rn(u, -1.0f);
            float u0 = __fadd_rn(__fmul_rn(0.9f, u), iv);
            float u1 = __fadd_rn(__fmul_rn(0.9f, d1), iv);
            u = sflag ? u1 : u0;
            sflag = (u > 1.0f);
            if (WRITE_ALL)
                sdst[(size_t)(st * 64 + t) * HH] = __float2half_rn(sflag ? 1.0f : 0.0f);
        }
        __syncthreads();
        if (st + 4 < 16) load_stage(st + 4);
    }
    if (!WRITE_ALL) SF[b * HH + h0 + tid] = sflag ? 1.0f : 0.0f;
}

// ---------------------------------------------------------------------------
__global__ void final_fc(const float* __restrict__ SF, const float* __restrict__ fcW,
                         const float* __restrict__ fcb, float* __restrict__ out)
{
    __shared__ float ss[HH];
    int b = blockIdx.x;
    for (int h = threadIdx.x; h < HH; h += blockDim.x)
        ss[h] = SF[b * HH + h];
    __syncthreads();

    int o = threadIdx.x;
    const float4* wrow = (const float4*)(fcW + (size_t)o * HH);
    float acc = 0.f;
#pragma unroll 4
    for (int h4 = 0; h4 < HH / 4; h4++) {
        float4 w = wrow[h4];
        float4 sv = *(const float4*)&ss[h4 * 4];
        acc += w.x * sv.x + w.y * sv.y + w.z * sv.z + w.w * sv.w;
    }
    out[b * OO + o] = acc + fcb[o];
}

// ---------------------------------------------------------------------------
extern "C" void kernel_launch(void* const* d_in, const int* in_sizes, int n_in,
                              void* d_out, int out_size)
{
    const float* x   = (const float*)d_in[0];
    const float* W0  = (const float*)d_in[1];
    const float* b0  = (const float*)d_in[2];
    const float* W1  = (const float*)d_in[3];
    const float* b1  = (const float*)d_in[4];
    const float* fcW = (const float*)d_in[5];
    const float* fcb = (const float*)d_in[6];
    float* out = (float*)d_out;

    float *I0p, *SFp; __half *S1p, *xh, *xl, *w0h, *w0l, *w1h, *w1l;
    cudaGetSymbolAddress((void**)&I0p, g_I0);
    cudaGetSymbolAddress((void**)&S1p, g_S1);
    cudaGetSymbolAddress((void**)&SFp, g_SF);
    cudaGetSymbolAddress((void**)&xh,  g_xh);
    cudaGetSymbolAddress((void**)&xl,  g_xl);
    cudaGetSymbolAddress((void**)&w0h, g_w0h);
    cudaGetSymbolAddress((void**)&w0l, g_w0l);
    cudaGetSymbolAddress((void**)&w1h, g_w1h);
    cudaGetSymbolAddress((void**)&w1l, g_w1l);

    const int SMEM1 = 3 * 4 * 128 * PHK * 2;   // 221184 B (split A)
    const int SMEM2 = 3 * 3 * 128 * PHK * 2;   // 165888 B (exact A)
    const int SMEML = 4 * 64 * 128 * 4;        // 131072 B
    cudaFuncSetAttribute((const void*)gemm_f16<true>,
                         cudaFuncAttributeMaxDynamicSharedMemorySize, SMEM1);
    cudaFuncSetAttribute((const void*)gemm_f16<false>,
                         cudaFuncAttributeMaxDynamicSharedMemorySize, SMEM2);
    cudaFuncSetAttribute((const void*)lif_scan<true>,
                         cudaFuncAttributeMaxDynamicSharedMemorySize, SMEML);
    cudaFuncSetAttribute((const void*)lif_scan<false>,
                         cudaFuncAttributeMaxDynamicSharedMemorySize, SMEML);

    // Pipeline resources (created/destroyed every call — capture-legal fork/join)
    cudaStream_t s1;
    cudaStreamCreateWithFlags(&s1, cudaStreamNonBlocking);
    cudaEvent_t eG1[2], eL1[2], eG2[2], eL2[2];
    for (int g = 0; g < 2; g++) {
        cudaEventCreateWithFlags(&eG1[g], cudaEventDisableTiming);
        cudaEventCreateWithFlags(&eL1[g], cudaEventDisableTiming);
        cudaEventCreateWithFlags(&eG2[g], cudaEventDisableTiming);
        cudaEventCreateWithFlags(&eL2[g], cudaEventDisableTiming);
    }

    conv_split<<<(MTOT * DD) / 1024, 256>>>(x,  xh,  xl);
    conv_split<<<(HH * DD) / 1024,   256>>>(W0, w0h, w0l);
    conv_split<<<(HH * HH) / 1024,   256>>>(W1, w1h, w1l);

    dim3 ggrid(HH / 128, MGRP / 128);          // (4, 128) per group
    const size_t gofsA = (size_t)MGRP * DD;    // x group stride (elements)
    const size_t gofsH = (size_t)MGRP * HH;    // I0/S1 group stride

    // ---- Layer 1: GEMM per group on stream 0, LIF overlapped on s1 ----
    for (int g = 0; g < 2; g++) {
        gemm_f16<true><<<ggrid, 512, SMEM1>>>(
            xh + g * gofsA, xl + g * gofsA, w0h, w0l, b0, I0p + g * gofsH, DD);
        cudaEventRecord(eG1[g], 0);
        cudaStreamWaitEvent(s1, eG1[g], 0);
        lif_scan<true><<<BGRP * 4, 128, SMEML, s1>>>(
            I0p + g * gofsH, S1p + g * gofsH, nullptr);
        cudaEventRecord(eL1[g], s1);
    }

    // ---- Layer 2: GEMM(g) waits LIF1(g); LIF2 overlapped on s1 ----
    for (int g = 0; g < 2; g++) {
        cudaStreamWaitEvent(0, eL1[g], 0);
        gemm_f16<false><<<ggrid, 512, SMEM2>>>(
            S1p + g * gofsH, nullptr, w1h, w1l, b1, I0p + g * gofsH, HH);
        cudaEventRecord(eG2[g], 0);
        cudaStreamWaitEvent(s1, eG2[g], 0);
        lif_scan<false><<<BGRP * 4, 128, SMEML, s1>>>(
            I0p + g * gofsH, nullptr, SFp + g * BGRP * HH);
        cudaEventRecord(eL2[g], s1);
    }

    // ---- Join and readout ----
    cudaStreamWaitEvent(0, eL2[0], 0);
    cudaStreamWaitEvent(0, eL2[1], 0);
    final_fc<<<BATCH, 256>>>(SFp, fcW, fcb, out);

    for (int g = 0; g < 2; g++) {
        cudaEventDestroy(eG1[g]); cudaEventDestroy(eL1[g]);
        cudaEventDestroy(eG2[g]); cudaEventDestroy(eL2[g]);
    }
    cudaStreamDestroy(s1);
}

// round 16
// speedup vs baseline: 1.0635x; 1.0635x over previous
#include <cuda_runtime.h>
#include <cuda_fp16.h>
#include <cstdint>

#define BATCH 32
#define TT    1024
#define DD    512
#define HH    512
#define OO    256
#define MTOT  (BATCH * TT)   // 32768

__device__ float  g_I0[(size_t)MTOT * HH];
__device__ __half g_S1[(size_t)MTOT * HH];
__device__ float  g_SF[BATCH * HH];
__device__ __half g_xh[(size_t)MTOT * DD];
__device__ __half g_xl[(size_t)MTOT * DD];
__device__ __half g_w0h[HH * DD], g_w0l[HH * DD];
__device__ __half g_w1h[HH * HH], g_w1l[HH * HH];

#define INV2048 4.8828125e-4f
#define PHK 72                     // smem row pitch in halves for BK=64

// ---------------------------------------------------------------------------
__device__ __forceinline__ uint32_t smem_u32(const void* p) {
    uint32_t a;
    asm("{ .reg .u64 t; cvta.to.shared.u64 t, %1; cvt.u32.u64 %0, t; }"
        : "=r"(a) : "l"(p));
    return a;
}
__device__ __forceinline__ void cp_async16(uint32_t dst, const void* src) {
    asm volatile("cp.async.cg.shared.global [%0], [%1], 16;" :: "r"(dst), "l"(src));
}
#define CP_COMMIT()  asm volatile("cp.async.commit_group;" ::: "memory")
#define CP_WAIT(n)   asm volatile("cp.async.wait_group %0;" :: "n"(n) : "memory")

__device__ __forceinline__ void mma_f16(float* d, const uint32_t* a, const uint32_t* b) {
    asm volatile(
        "mma.sync.aligned.m16n8k16.row.col.f32.f16.f16.f32 "
        "{%0,%1,%2,%3}, {%4,%5,%6,%7}, {%8,%9}, {%0,%1,%2,%3};"
        : "+f"(d[0]), "+f"(d[1]), "+f"(d[2]), "+f"(d[3])
        : "r"(a[0]), "r"(a[1]), "r"(a[2]), "r"(a[3]), "r"(b[0]), "r"(b[1]));
}
#define LDSM_X4(r0, r1, r2, r3, addr) \
    asm volatile("ldmatrix.sync.aligned.m8n8.x4.shared.b16 {%0,%1,%2,%3}, [%4];" \
                 : "=r"(r0), "=r"(r1), "=r"(r2), "=r"(r3) : "r"(addr))

// ---------------------------------------------------------------------------
__global__ __launch_bounds__(256) void conv_split(const float* __restrict__ X,
                                                  __half* __restrict__ Xh,
                                                  __half* __restrict__ Xl)
{
    int i = (blockIdx.x * 256 + threadIdx.x) * 4;
    float4 v = *(const float4*)(X + i);
    __half h0 = __float2half_rn(v.x), h1 = __float2half_rn(v.y);
    __half h2 = __float2half_rn(v.z), h3 = __float2half_rn(v.w);
    __half l0 = __float2half_rn((v.x - __half2float(h0)) * 2048.f);
    __half l1 = __float2half_rn((v.y - __half2float(h1)) * 2048.f);
    __half l2 = __float2half_rn((v.z - __half2float(h2)) * 2048.f);
    __half l3 = __float2half_rn((v.w - __half2float(h3)) * 2048.f);
    __half2 hv0 = __halves2half2(h0, h1), hv1 = __halves2half2(h2, h3);
    __half2 lv0 = __halves2half2(l0, l1), lv1 = __halves2half2(l2, l3);
    uint2 ho = { *(uint32_t*)&hv0, *(uint32_t*)&hv1 };
    uint2 lo = { *(uint32_t*)&lv0, *(uint32_t*)&lv1 };
    *(uint2*)(Xh + i) = ho;
    *(uint2*)(Xl + i) = lo;
}

// ---------------------------------------------------------------------------
// fp16 GEMM — champion structure (R13/R14): CTA 128x128, BK=64, 512 thr /
// 16 warps (4x4, 32x32 warp tiles), 3-stage cp.async, B frags double-
// buffered, two barriers per chunk. Dual fp32 accumulators (H + L/2048).
// ---------------------------------------------------------------------------
struct BFrag { uint32_t bh[4][2]; uint32_t bl[4][2]; };

template <bool SPLIT_A>
__global__ __launch_bounds__(512, 1) void gemm_f16(
    const __half* __restrict__ Ahg, const __half* __restrict__ Alg,
    const __half* __restrict__ Bhg, const __half* __restrict__ Blg,
    const float* __restrict__ bias, float* __restrict__ C, int K)
{
    constexpr int TILE_H = 128 * PHK;
    constexpr int NT     = SPLIT_A ? 4 : 3;
    constexpr int STG_H  = NT * TILE_H;
    constexpr int OFF_AH = 0;
    constexpr int OFF_AL = TILE_H;               // iff SPLIT_A
    constexpr int OFF_BH = (SPLIT_A ? 2 : 1) * TILE_H;
    constexpr int OFF_BL = OFF_BH + TILE_H;
    extern __shared__ __half sh[];
    const uint32_t sb = smem_u32(sh);

    const int tid = threadIdx.x, lid = tid & 31, wid = tid >> 5;
    const int bm = blockIdx.y * 128, bn = blockIdx.x * 128;
    const int warp_m = (wid >> 2) * 32, warp_n = (wid & 3) * 32;

    float accH[2][4][4], accL[2][4][4];
#pragma unroll
    for (int i = 0; i < 2; i++)
#pragma unroll
        for (int j = 0; j < 4; j++)
#pragma unroll
            for (int f = 0; f < 4; f++) { accH[i][j][f] = 0.f; accL[i][j][f] = 0.f; }

    const int NC = K / 64;
    const int lr  = tid >> 3;
    const int lc8 = (tid & 7) * 8;

    auto ld_tile = [&](const __half* G, int grow, int kc, uint32_t dst_halves,
                       uint32_t base) {
        cp_async16(base + (dst_halves + (uint32_t)lr * PHK + lc8) * 2,
                   G + (size_t)(grow + lr) * K + kc + lc8);
        cp_async16(base + (dst_halves + (uint32_t)(lr + 64) * PHK + lc8) * 2,
                   G + (size_t)(grow + lr + 64) * K + kc + lc8);
    };
    auto load_stage = [&](int c) {
        const int kc = c * 64;
        uint32_t base = sb + (uint32_t)(c % 3) * STG_H * 2;
        ld_tile(Ahg, bm, kc, OFF_AH, base);
        if (SPLIT_A) ld_tile(Alg, bm, kc, OFF_AL, base);
        ld_tile(Bhg, bn, kc, OFF_BH, base);
        ld_tile(Blg, bn, kc, OFF_BL, base);
        CP_COMMIT();
    };

    const uint32_t arow = ((uint32_t)(warp_m + (lid & 15)) * PHK + ((lid >> 4) << 3)) * 2;
    const uint32_t brow = ((uint32_t)(warp_n + ((lid >> 4) << 3) + (lid & 7)) * PHK
                          + (((lid >> 3) & 1) << 3)) * 2;

    uint32_t ah[2][4], al[2][4];
    auto ldA = [&](uint32_t stage_base, int ks) {
        uint32_t a0 = stage_base + OFF_AH * 2 + arow + (uint32_t)(ks * 16) * 2;
        LDSM_X4(ah[0][0], ah[0][1], ah[0][2], ah[0][3], a0);
        LDSM_X4(ah[1][0], ah[1][1], ah[1][2], ah[1][3], a0 + 16u * PHK * 2);
        if (SPLIT_A) {
            uint32_t a1 = stage_base + OFF_AL * 2 + arow + (uint32_t)(ks * 16) * 2;
            LDSM_X4(al[0][0], al[0][1], al[0][2], al[0][3], a1);
            LDSM_X4(al[1][0], al[1][1], al[1][2], al[1][3], a1 + 16u * PHK * 2);
        }
    };
    auto ldB = [&](BFrag& f, uint32_t stage_base, int ks) {
        uint32_t bH = stage_base + OFF_BH * 2 + brow + (uint32_t)(ks * 16) * 2;
        uint32_t bL = stage_base + OFF_BL * 2 + brow + (uint32_t)(ks * 16) * 2;
#pragma unroll
        for (int jp = 0; jp < 2; jp++) {
            uint32_t off = (uint32_t)jp * 16 * PHK * 2;
            LDSM_X4(f.bh[2*jp][0], f.bh[2*jp][1], f.bh[2*jp+1][0], f.bh[2*jp+1][1], bH + off);
            LDSM_X4(f.bl[2*jp][0], f.bl[2*jp][1], f.bl[2*jp+1][0], f.bl[2*jp+1][1], bL + off);
        }
    };
    auto mma_all = [&](const BFrag& f) {
#pragma unroll
        for (int i = 0; i < 2; i++)
#pragma unroll
            for (int j = 0; j < 4; j++)
                mma_f16(accH[i][j], ah[i], f.bh[j]);
#pragma unroll
        for (int i = 0; i < 2; i++)
#pragma unroll
            for (int j = 0; j < 4; j++)
                mma_f16(accL[i][j], ah[i], f.bl[j]);
        if (SPLIT_A) {
#pragma unroll
            for (int i = 0; i < 2; i++)
#pragma unroll
                for (int j = 0; j < 4; j++)
                    mma_f16(accL[i][j], al[i], f.bh[j]);
        }
    };

    load_stage(0); load_stage(1); load_stage(2);

    BFrag fb0, fb1;
    CP_WAIT(2);
    __syncthreads();
    ldB(fb0, sb, 0);                             // (chunk 0, ks0)

    for (int c = 0; c < NC; c++) {
        if (c < NC - 2) { CP_WAIT(1); } else { CP_WAIT(0); }
        __syncthreads();
        uint32_t st_c  = sb + (uint32_t)(c % 3) * STG_H * 2;
        uint32_t st_c1 = sb + (uint32_t)((c + 1) % 3) * STG_H * 2;

        ldA(st_c, 0); ldB(fb1, st_c, 1); mma_all(fb0);
        ldA(st_c, 1); ldB(fb0, st_c, 2); mma_all(fb1);
        ldA(st_c, 2); ldB(fb1, st_c, 3); mma_all(fb0);
        ldA(st_c, 3);
        if (c + 1 < NC) ldB(fb0, st_c1, 0);
        mma_all(fb1);

        __syncthreads();
        if (c + 3 < NC) load_stage(c + 3);
    }

#pragma unroll
    for (int i = 0; i < 2; i++) {
        int row0 = bm + warp_m + i * 16 + (lid >> 2);
#pragma unroll
        for (int j = 0; j < 4; j++) {
            int col = bn + warp_n + j * 8 + (lid & 3) * 2;
            float b0 = bias[col], b1 = bias[col + 1];
            float2 v0 = { accH[i][j][0] + accL[i][j][0] * INV2048 + b0,
                          accH[i][j][1] + accL[i][j][1] * INV2048 + b1 };
            float2 v1 = { accH[i][j][2] + accL[i][j][2] * INV2048 + b0,
                          accH[i][j][3] + accL[i][j][3] * INV2048 + b1 };
            *(float2*)(C + (size_t)row0 * HH + col) = v0;
            *(float2*)(C + (size_t)(row0 + 8) * HH + col) = v1;
        }
    }
}

// ---------------------------------------------------------------------------
// LIF scan, 4-stage cp.async pipeline + speculative dual-path update:
//   u0 = rn(rn(0.9*u) + i)          (s==0 path: u - 0 == u exactly)
//   u1 = rn(rn(0.9*rn(u-1)) + i)    (s==1 path: rn(u-1) == rn(u-s))
//   u  = s ? u1 : u0 ; s = (u > 1)
// Bit-identical to reference; dependency chain 25 -> 17 cyc/step.
// ---------------------------------------------------------------------------
template <bool WRITE_ALL>
__global__ __launch_bounds__(128) void lif_scan(const float* __restrict__ I,
                                                __half* __restrict__ S,
                                                float* __restrict__ SF)
{
    extern __shared__ float buf[];
    const int tid = threadIdx.x;
    const int b  = blockIdx.x >> 2;
    const int h0 = (blockIdx.x & 3) * 128;
    const float* src = I + (size_t)b * TT * HH + h0;
    __half* sdst = WRITE_ALL ? (S + (size_t)b * TT * HH + h0 + tid) : nullptr;

    const uint32_t sb = smem_u32(buf);
    constexpr int STAGE_W = 64 * 128;

    auto load_stage = [&](int st) {
        const float* g = src + (size_t)st * 64 * HH;
        uint32_t d = sb + (uint32_t)(st & 3) * STAGE_W * 4;
#pragma unroll
        for (int s = 0; s < 16; s++) {
            int c = tid + s * 128;
            int t = c >> 5, off = (c & 31) * 4;
            cp_async16(d + (uint32_t)(t * 128 + off) * 4, g + (size_t)t * HH + off);
        }
        CP_COMMIT();
    };

    load_stage(0); load_stage(1); load_stage(2); load_stage(3);

    float u = 0.f;
    bool sflag = false;
    for (int st = 0; st < 16; st++) {
        CP_WAIT(3);
        __syncthreads();
        const float* stage = buf + (st & 3) * STAGE_W;
#pragma unroll
        for (int t = 0; t < 64; t++) {
            float iv = stage[t * 128 + tid];
            float d1 = __fadd_rn(u, -1.0f);
            float u0 = __fadd_rn(__fmul_rn(0.9f, u), iv);
            float u1 = __fadd_rn(__fmul_rn(0.9f, d1), iv);
            u = sflag ? u1 : u0;
            sflag = (u > 1.0f);
            if (WRITE_ALL)
                sdst[(size_t)(st * 64 + t) * HH] = __float2half_rn(sflag ? 1.0f : 0.0f);
        }
        __syncthreads();
        if (st + 4 < 16) load_stage(st + 4);
    }
    if (!WRITE_ALL) SF[b * HH + h0 + tid] = sflag ? 1.0f : 0.0f;
}

// ---------------------------------------------------------------------------
__global__ void final_fc(const float* __restrict__ SF, const float* __restrict__ fcW,
                         const float* __restrict__ fcb, float* __restrict__ out)
{
    __shared__ float ss[HH];
    int b = blockIdx.x;
    for (int h = threadIdx.x; h < HH; h += blockDim.x)
        ss[h] = SF[b * HH + h];
    __syncthreads();

    int o = threadIdx.x;
    const float4* wrow = (const float4*)(fcW + (size_t)o * HH);
    float acc = 0.f;
#pragma unroll 4
    for (int h4 = 0; h4 < HH / 4; h4++) {
        float4 w = wrow[h4];
        float4 sv = *(const float4*)&ss[h4 * 4];
        acc += w.x * sv.x + w.y * sv.y + w.z * sv.z + w.w * sv.w;
    }
    out[b * OO + o] = acc + fcb[o];
}

// ---------------------------------------------------------------------------
extern "C" void kernel_launch(void* const* d_in, const int* in_sizes, int n_in,
                              void* d_out, int out_size)
{
    const float* x   = (const float*)d_in[0];
    const float* W0  = (const float*)d_in[1];
    const float* b0  = (const float*)d_in[2];
    const float* W1  = (const float*)d_in[3];
    const float* b1  = (const float*)d_in[4];
    const float* fcW = (const float*)d_in[5];
    const float* fcb = (const float*)d_in[6];
    float* out = (float*)d_out;

    float *I0p, *SFp; __half *S1p, *xh, *xl, *w0h, *w0l, *w1h, *w1l;
    cudaGetSymbolAddress((void**)&I0p, g_I0);
    cudaGetSymbolAddress((void**)&S1p, g_S1);
    cudaGetSymbolAddress((void**)&SFp, g_SF);
    cudaGetSymbolAddress((void**)&xh,  g_xh);
    cudaGetSymbolAddress((void**)&xl,  g_xl);
    cudaGetSymbolAddress((void**)&w0h, g_w0h);
    cudaGetSymbolAddress((void**)&w0l, g_w0l);
    cudaGetSymbolAddress((void**)&w1h, g_w1h);
    cudaGetSymbolAddress((void**)&w1l, g_w1l);

    const int SMEM1 = 3 * 4 * 128 * PHK * 2;   // 221184 B (split A)
    const int SMEM2 = 3 * 3 * 128 * PHK * 2;   // 165888 B (exact A)
    const int SMEML = 4 * 64 * 128 * 4;        // 131072 B
    cudaFuncSetAttribute((const void*)gemm_f16<true>,
                         cudaFuncAttributeMaxDynamicSharedMemorySize, SMEM1);
    cudaFuncSetAttribute((const void*)gemm_f16<false>,
                         cudaFuncAttributeMaxDynamicSharedMemorySize, SMEM2);
    cudaFuncSetAttribute((const void*)lif_scan<true>,
                         cudaFuncAttributeMaxDynamicSharedMemorySize, SMEML);
    cudaFuncSetAttribute((const void*)lif_scan<false>,
                         cudaFuncAttributeMaxDynamicSharedMemorySize, SMEML);

    conv_split<<<(MTOT * DD) / 1024, 256>>>(x,  xh,  xl);
    conv_split<<<(HH * DD) / 1024,   256>>>(W0, w0h, w0l);
    conv_split<<<(HH * HH) / 1024,   256>>>(W1, w1h, w1l);

    dim3 ggrid(HH / 128, MTOT / 128);   // (4, 256)

    gemm_f16<true><<<ggrid, 512, SMEM1>>>(xh, xl, w0h, w0l, b0, I0p, DD);
    lif_scan<true><<<128, 128, SMEML>>>(I0p, S1p, nullptr);

    gemm_f16<false><<<ggrid, 512, SMEM2>>>(S1p, nullptr, w1h, w1l, b1, I0p, HH);
    lif_scan<false><<<128, 128, SMEML>>>(I0p, nullptr, SFp);

    final_fc<<<BATCH, 256>>>(SFp, fcW, fcb, out);
}

// round 17
// speedup vs baseline: 1.0649x; 1.0014x over previous
#include <cuda_runtime.h>
#include <cuda_fp16.h>
#include <cstdint>

#define BATCH 32
#define TT    1024
#define DD    512
#define HH    512
#define OO    256
#define MTOT  (BATCH * TT)   // 32768

__device__ float  g_I0[(size_t)MTOT * HH];
__device__ __half g_S1[(size_t)MTOT * HH];
__device__ float  g_SF[BATCH * HH];
__device__ __half g_xh[(size_t)MTOT * DD];
__device__ __half g_xl[(size_t)MTOT * DD];
__device__ __half g_w0h[HH * DD], g_w0l[HH * DD];
__device__ __half g_w1h[HH * HH], g_w1l[HH * HH];

#define INV2048 4.8828125e-4f
#define PHK 72                     // smem row pitch in halves for BK=64

// ---------------------------------------------------------------------------
__device__ __forceinline__ uint32_t smem_u32(const void* p) {
    uint32_t a;
    asm("{ .reg .u64 t; cvta.to.shared.u64 t, %1; cvt.u32.u64 %0, t; }"
        : "=r"(a) : "l"(p));
    return a;
}
__device__ __forceinline__ void cp_async16(uint32_t dst, const void* src) {
    asm volatile("cp.async.cg.shared.global [%0], [%1], 16;" :: "r"(dst), "l"(src));
}
#define CP_COMMIT()  asm volatile("cp.async.commit_group;" ::: "memory")
#define CP_WAIT(n)   asm volatile("cp.async.wait_group %0;" :: "n"(n) : "memory")

__device__ __forceinline__ void mma_f16(float* d, const uint32_t* a, const uint32_t* b) {
    asm volatile(
        "mma.sync.aligned.m16n8k16.row.col.f32.f16.f16.f32 "
        "{%0,%1,%2,%3}, {%4,%5,%6,%7}, {%8,%9}, {%0,%1,%2,%3};"
        : "+f"(d[0]), "+f"(d[1]), "+f"(d[2]), "+f"(d[3])
        : "r"(a[0]), "r"(a[1]), "r"(a[2]), "r"(a[3]), "r"(b[0]), "r"(b[1]));
}
#define LDSM_X4(r0, r1, r2, r3, addr) \
    asm volatile("ldmatrix.sync.aligned.m8n8.x4.shared.b16 {%0,%1,%2,%3}, [%4];" \
                 : "=r"(r0), "=r"(r1), "=r"(r2), "=r"(r3) : "r"(addr))

// ---------------------------------------------------------------------------
__global__ __launch_bounds__(256) void conv_split(const float* __restrict__ X,
                                                  __half* __restrict__ Xh,
                                                  __half* __restrict__ Xl)
{
    int i = (blockIdx.x * 256 + threadIdx.x) * 4;
    float4 v = *(const float4*)(X + i);
    __half h0 = __float2half_rn(v.x), h1 = __float2half_rn(v.y);
    __half h2 = __float2half_rn(v.z), h3 = __float2half_rn(v.w);
    __half l0 = __float2half_rn((v.x - __half2float(h0)) * 2048.f);
    __half l1 = __float2half_rn((v.y - __half2float(h1)) * 2048.f);
    __half l2 = __float2half_rn((v.z - __half2float(h2)) * 2048.f);
    __half l3 = __float2half_rn((v.w - __half2float(h3)) * 2048.f);
    __half2 hv0 = __halves2half2(h0, h1), hv1 = __halves2half2(h2, h3);
    __half2 lv0 = __halves2half2(l0, l1), lv1 = __halves2half2(l2, l3);
    uint2 ho = { *(uint32_t*)&hv0, *(uint32_t*)&hv1 };
    uint2 lo = { *(uint32_t*)&lv0, *(uint32_t*)&lv1 };
    *(uint2*)(Xh + i) = ho;
    *(uint2*)(Xl + i) = lo;
}

// ---------------------------------------------------------------------------
// fp16 GEMM — champion structure (R13/R14/R15, measured optimum, UNCHANGED):
// CTA 128x128, BK=64, 512 thr / 16 warps (4x4, 32x32 warp tiles), 3-stage
// cp.async, B frags double-buffered, two barriers per chunk.
// Dual fp32 accumulators (H + L/2048); bitwise-stable.
// ---------------------------------------------------------------------------
struct BFrag { uint32_t bh[4][2]; uint32_t bl[4][2]; };

template <bool SPLIT_A>
__global__ __launch_bounds__(512, 1) void gemm_f16(
    const __half* __restrict__ Ahg, const __half* __restrict__ Alg,
    const __half* __restrict__ Bhg, const __half* __restrict__ Blg,
    const float* __restrict__ bias, float* __restrict__ C, int K)
{
    constexpr int TILE_H = 128 * PHK;
    constexpr int NT     = SPLIT_A ? 4 : 3;
    constexpr int STG_H  = NT * TILE_H;
    constexpr int OFF_AH = 0;
    constexpr int OFF_AL = TILE_H;               // iff SPLIT_A
    constexpr int OFF_BH = (SPLIT_A ? 2 : 1) * TILE_H;
    constexpr int OFF_BL = OFF_BH + TILE_H;
    extern __shared__ __half sh[];
    const uint32_t sb = smem_u32(sh);

    const int tid = threadIdx.x, lid = tid & 31, wid = tid >> 5;
    const int bm = blockIdx.y * 128, bn = blockIdx.x * 128;
    const int warp_m = (wid >> 2) * 32, warp_n = (wid & 3) * 32;

    float accH[2][4][4], accL[2][4][4];
#pragma unroll
    for (int i = 0; i < 2; i++)
#pragma unroll
        for (int j = 0; j < 4; j++)
#pragma unroll
            for (int f = 0; f < 4; f++) { accH[i][j][f] = 0.f; accL[i][j][f] = 0.f; }

    const int NC = K / 64;
    const int lr  = tid >> 3;
    const int lc8 = (tid & 7) * 8;

    auto ld_tile = [&](const __half* G, int grow, int kc, uint32_t dst_halves,
                       uint32_t base) {
        cp_async16(base + (dst_halves + (uint32_t)lr * PHK + lc8) * 2,
                   G + (size_t)(grow + lr) * K + kc + lc8);
        cp_async16(base + (dst_halves + (uint32_t)(lr + 64) * PHK + lc8) * 2,
                   G + (size_t)(grow + lr + 64) * K + kc + lc8);
    };
    auto load_stage = [&](int c) {
        const int kc = c * 64;
        uint32_t base = sb + (uint32_t)(c % 3) * STG_H * 2;
        ld_tile(Ahg, bm, kc, OFF_AH, base);
        if (SPLIT_A) ld_tile(Alg, bm, kc, OFF_AL, base);
        ld_tile(Bhg, bn, kc, OFF_BH, base);
        ld_tile(Blg, bn, kc, OFF_BL, base);
        CP_COMMIT();
    };

    const uint32_t arow = ((uint32_t)(warp_m + (lid & 15)) * PHK + ((lid >> 4) << 3)) * 2;
    const uint32_t brow = ((uint32_t)(warp_n + ((lid >> 4) << 3) + (lid & 7)) * PHK
                          + (((lid >> 3) & 1) << 3)) * 2;

    uint32_t ah[2][4], al[2][4];
    auto ldA = [&](uint32_t stage_base, int ks) {
        uint32_t a0 = stage_base + OFF_AH * 2 + arow + (uint32_t)(ks * 16) * 2;
        LDSM_X4(ah[0][0], ah[0][1], ah[0][2], ah[0][3], a0);
        LDSM_X4(ah[1][0], ah[1][1], ah[1][2], ah[1][3], a0 + 16u * PHK * 2);
        if (SPLIT_A) {
            uint32_t a1 = stage_base + OFF_AL * 2 + arow + (uint32_t)(ks * 16) * 2;
            LDSM_X4(al[0][0], al[0][1], al[0][2], al[0][3], a1);
            LDSM_X4(al[1][0], al[1][1], al[1][2], al[1][3], a1 + 16u * PHK * 2);
        }
    };
    auto ldB = [&](BFrag& f, uint32_t stage_base, int ks) {
        uint32_t bH = stage_base + OFF_BH * 2 + brow + (uint32_t)(ks * 16) * 2;
        uint32_t bL = stage_base + OFF_BL * 2 + brow + (uint32_t)(ks * 16) * 2;
#pragma unroll
        for (int jp = 0; jp < 2; jp++) {
            uint32_t off = (uint32_t)jp * 16 * PHK * 2;
            LDSM_X4(f.bh[2*jp][0], f.bh[2*jp][1], f.bh[2*jp+1][0], f.bh[2*jp+1][1], bH + off);
            LDSM_X4(f.bl[2*jp][0], f.bl[2*jp][1], f.bl[2*jp+1][0], f.bl[2*jp+1][1], bL + off);
        }
    };
    auto mma_all = [&](const BFrag& f) {
#pragma unroll
        for (int i = 0; i < 2; i++)
#pragma unroll
            for (int j = 0; j < 4; j++)
                mma_f16(accH[i][j], ah[i], f.bh[j]);
#pragma unroll
        for (int i = 0; i < 2; i++)
#pragma unroll
            for (int j = 0; j < 4; j++)
                mma_f16(accL[i][j], ah[i], f.bl[j]);
        if (SPLIT_A) {
#pragma unroll
            for (int i = 0; i < 2; i++)
#pragma unroll
                for (int j = 0; j < 4; j++)
                    mma_f16(accL[i][j], al[i], f.bh[j]);
        }
    };

    load_stage(0); load_stage(1); load_stage(2);

    BFrag fb0, fb1;
    CP_WAIT(2);
    __syncthreads();
    ldB(fb0, sb, 0);                             // (chunk 0, ks0)

    for (int c = 0; c < NC; c++) {
        if (c < NC - 2) { CP_WAIT(1); } else { CP_WAIT(0); }
        __syncthreads();
        uint32_t st_c  = sb + (uint32_t)(c % 3) * STG_H * 2;
        uint32_t st_c1 = sb + (uint32_t)((c + 1) % 3) * STG_H * 2;

        ldA(st_c, 0); ldB(fb1, st_c, 1); mma_all(fb0);
        ldA(st_c, 1); ldB(fb0, st_c, 2); mma_all(fb1);
        ldA(st_c, 2); ldB(fb1, st_c, 3); mma_all(fb0);
        ldA(st_c, 3);
        if (c + 1 < NC) ldB(fb0, st_c1, 0);
        mma_all(fb1);

        __syncthreads();
        if (c + 3 < NC) load_stage(c + 3);
    }

#pragma unroll
    for (int i = 0; i < 2; i++) {
        int row0 = bm + warp_m + i * 16 + (lid >> 2);
#pragma unroll
        for (int j = 0; j < 4; j++) {
            int col = bn + warp_n + j * 8 + (lid & 3) * 2;
            float b0 = bias[col], b1 = bias[col + 1];
            float2 v0 = { accH[i][j][0] + accL[i][j][0] * INV2048 + b0,
                          accH[i][j][1] + accL[i][j][1] * INV2048 + b1 };
            float2 v1 = { accH[i][j][2] + accL[i][j][2] * INV2048 + b0,
                          accH[i][j][3] + accL[i][j][3] * INV2048 + b1 };
            *(float2*)(C + (size_t)row0 * HH + col) = v0;
            *(float2*)(C + (size_t)(row0 + 8) * HH + col) = v1;
        }
    }
}

// ---------------------------------------------------------------------------
// LIF scan — 64 channels / 64 threads per block, grid 256 (full SM coverage,
// up to 3 blocks/SM). 4-stage cp.async ring (16KB stages), iv consumed in
// 8-deep register batches (LDS latency off the recurrence chain).
// Speculative dual-path update (bit-identical to reference):
//   u0 = rn(rn(0.9*u) + i); u1 = rn(rn(0.9*rn(u-1)) + i); u = s ? u1 : u0.
// ---------------------------------------------------------------------------
template <bool WRITE_ALL>
__global__ __launch_bounds__(64) void lif_scan(const float* __restrict__ I,
                                               __half* __restrict__ S,
                                               float* __restrict__ SF)
{
    extern __shared__ float buf[];                 // 4 * 64 * 64 floats (64KB)
    const int tid = threadIdx.x;
    const int b  = blockIdx.x >> 3;                // 0..31
    const int h0 = (blockIdx.x & 7) * 64;
    const float* src = I + (size_t)b * TT * HH + h0;
    __half* sdst = WRITE_ALL ? (S + (size_t)b * TT * HH + h0 + tid) : nullptr;

    const uint32_t sb = smem_u32(buf);
    constexpr int STAGE_W = 64 * 64;               // floats per stage

    auto load_stage = [&](int st) {
        const float* g = src + (size_t)st * 64 * HH;
        uint32_t d = sb + (uint32_t)(st & 3) * STAGE_W * 4;
#pragma unroll
        for (int s = 0; s < 16; s++) {
            int c = tid + s * 64;                  // 0..1023
            int t = c >> 4, off = (c & 15) * 4;    // 16 x 16B chunks per 256B row
            cp_async16(d + (uint32_t)(t * 64 + off) * 4, g + (size_t)t * HH + off);
        }
        CP_COMMIT();
    };

    load_stage(0); load_stage(1); load_stage(2); load_stage(3);

    float u = 0.f;
    bool sflag = false;
    for (int st = 0; st < 16; st++) {
        CP_WAIT(3);
        __syncthreads();
        const float* stage = buf + (st & 3) * STAGE_W;
#pragma unroll
        for (int t0 = 0; t0 < 64; t0 += 8) {
            float iv[8];
#pragma unroll
            for (int j = 0; j < 8; j++)            // 8 independent LDS up front
                iv[j] = stage[(t0 + j) * 64 + tid];
#pragma unroll
            for (int j = 0; j < 8; j++) {
                float d1 = __fadd_rn(u, -1.0f);
                float u0 = __fadd_rn(__fmul_rn(0.9f, u), iv[j]);
                float u1 = __fadd_rn(__fmul_rn(0.9f, d1), iv[j]);
                u = sflag ? u1 : u0;
                sflag = (u > 1.0f);
                if (WRITE_ALL)
                    sdst[(size_t)(st * 64 + t0 + j) * HH] =
                        __float2half_rn(sflag ? 1.0f : 0.0f);
            }
        }
        __syncthreads();
        if (st + 4 < 16) load_stage(st + 4);
    }
    if (!WRITE_ALL) SF[b * HH + h0 + tid] = sflag ? 1.0f : 0.0f;
}

// ---------------------------------------------------------------------------
__global__ void final_fc(const float* __restrict__ SF, const float* __restrict__ fcW,
                         const float* __restrict__ fcb, float* __restrict__ out)
{
    __shared__ float ss[HH];
    int b = blockIdx.x;
    for (int h = threadIdx.x; h < HH; h += blockDim.x)
        ss[h] = SF[b * HH + h];
    __syncthreads();

    int o = threadIdx.x;
    const float4* wrow = (const float4*)(fcW + (size_t)o * HH);
    float acc = 0.f;
#pragma unroll 4
    for (int h4 = 0; h4 < HH / 4; h4++) {
        float4 w = wrow[h4];
        float4 sv = *(const float4*)&ss[h4 * 4];
        acc += w.x * sv.x + w.y * sv.y + w.z * sv.z + w.w * sv.w;
    }
    out[b * OO + o] = acc + fcb[o];
}

// ---------------------------------------------------------------------------
extern "C" void kernel_launch(void* const* d_in, const int* in_sizes, int n_in,
                              void* d_out, int out_size)
{
    const float* x   = (const float*)d_in[0];
    const float* W0  = (const float*)d_in[1];
    const float* b0  = (const float*)d_in[2];
    const float* W1  = (const float*)d_in[3];
    const float* b1  = (const float*)d_in[4];
    const float* fcW = (const float*)d_in[5];
    const float* fcb = (const float*)d_in[6];
    float* out = (float*)d_out;

    float *I0p, *SFp; __half *S1p, *xh, *xl, *w0h, *w0l, *w1h, *w1l;
    cudaGetSymbolAddress((void**)&I0p, g_I0);
    cudaGetSymbolAddress((void**)&S1p, g_S1);
    cudaGetSymbolAddress((void**)&SFp, g_SF);
    cudaGetSymbolAddress((void**)&xh,  g_xh);
    cudaGetSymbolAddress((void**)&xl,  g_xl);
    cudaGetSymbolAddress((void**)&w0h, g_w0h);
    cudaGetSymbolAddress((void**)&w0l, g_w0l);
    cudaGetSymbolAddress((void**)&w1h, g_w1h);
    cudaGetSymbolAddress((void**)&w1l, g_w1l);

    const int SMEM1 = 3 * 4 * 128 * PHK * 2;   // 221184 B (split A)
    const int SMEM2 = 3 * 3 * 128 * PHK * 2;   // 165888 B (exact A)
    const int SMEML = 4 * 64 * 64 * 4;         //  65536 B
    cudaFuncSetAttribute((const void*)gemm_f16<true>,
                         cudaFuncAttributeMaxDynamicSharedMemorySize, SMEM1);
    cudaFuncSetAttribute((const void*)gemm_f16<false>,
                         cudaFuncAttributeMaxDynamicSharedMemorySize, SMEM2);
    cudaFuncSetAttribute((const void*)lif_scan<true>,
                         cudaFuncAttributeMaxDynamicSharedMemorySize, SMEML);
    cudaFuncSetAttribute((const void*)lif_scan<false>,
                         cudaFuncAttributeMaxDynamicSharedMemorySize, SMEML);

    conv_split<<<(MTOT * DD) / 1024, 256>>>(x,  xh,  xl);
    conv_split<<<(HH * DD) / 1024,   256>>>(W0, w0h, w0l);
    conv_split<<<(HH * HH) / 1024,   256>>>(W1, w1h, w1l);

    dim3 ggrid(HH / 128, MTOT / 128);   // (4, 256)

    gemm_f16<true><<<ggrid, 512, SMEM1>>>(xh, xl, w0h, w0l, b0, I0p, DD);
    lif_scan<true><<<256, 64, SMEML>>>(I0p, S1p, nullptr);

    gemm_f16<false><<<ggrid, 512, SMEM2>>>(S1p, nullptr, w1h, w1l, b1, I0p, HH);
    lif_scan<false><<<256, 64, SMEML>>>(I0p, nullptr, SFp);

    final_fc<<<BATCH, 256>>>(SFp, fcW, fcb, out);
}